// round 16
// baseline (speedup 1.0000x reference)
#include <cuda_runtime.h>
#include <cuda_bf16.h>
#include <cstdint>

typedef unsigned long long ull;

#define PAIRS 1024
#define DD 256
#define QL 16

// ---------------- persistent scratch / precomputed ----------------
__device__ __nv_bfloat16 g_Aebf[256 * 256];  // M^T: [e][d] = M[d][e], bf16 (MMA B operand)
__device__ float    g_WvT[256 * 256];        // WvT[j][d] = vw_w[d][j]
__device__ float    g_u[256];
__device__ float    g_w[256];
__device__ float    g_c;
__device__ int      g_mask_mode;             // 0=u8 bool, 1=int32, 2=float32
__device__ unsigned g_Qtu[16384 * 128];      // Q-tilde bf16x2 words
__device__ float    g_ta[PAIRS * 256];       // raw ta (pre-softmax)
__device__ float    g_attn[PAIRS * 256];     // softmax weights per pair
__device__ float    g_tvh[2 * PAIRS * 256];  // attn.v partials per v-half
__device__ float    g_sA[PAIRS];             // 1 if any unmasked else 0
__device__ float    g_opart[2 * PAIRS * 256];// split-K partials [kc][row][c]

__device__ __forceinline__ unsigned f2bf(float a, float b) {
    __nv_bfloat162 h = __floats2bfloat162_rn(a, b);
    return *reinterpret_cast<unsigned*>(&h);
}
__device__ __forceinline__ uint32_t smem_to_u32(const void* p) {
    uint32_t a;
    asm("{ .reg .u64 tmp; cvta.to.shared.u64 tmp, %1; cvt.u32.u64 %0, tmp; }" : "=r"(a) : "l"(p));
    return a;
}
__device__ __forceinline__ void ldsm4(unsigned* r, uint32_t addr) {
    asm volatile("ldmatrix.sync.aligned.m8n8.x4.shared.b16 {%0,%1,%2,%3}, [%4];"
        : "=r"(r[0]), "=r"(r[1]), "=r"(r[2]), "=r"(r[3]) : "r"(addr));
}
__device__ __forceinline__ void mma16816(float* c, const unsigned* a, unsigned b0, unsigned b1) {
    asm volatile(
        "mma.sync.aligned.m16n8k16.row.col.f32.bf16.bf16.f32 "
        "{%0,%1,%2,%3}, {%4,%5,%6,%7}, {%8,%9}, {%0,%1,%2,%3};"
        : "+f"(c[0]), "+f"(c[1]), "+f"(c[2]), "+f"(c[3])
        : "r"(a[0]), "r"(a[1]), "r"(a[2]), "r"(a[3]), "r"(b0), "r"(b1));
}

// ---------------- setup kernel ----------------
__global__ void setup_kernel(const float* __restrict__ qw_w, const float* __restrict__ qw_b,
                             const float* __restrict__ kw_w, const float* __restrict__ kw_b,
                             const float* __restrict__ vw_w, const void* __restrict__ maskp)
{
    const int b = blockIdx.x;
    const int t = threadIdx.x;
    if (b < 128) {
        const int e0 = b * 2;
        float a0 = 0.f, a1 = 0.f;
        for (int cb = 0; cb < 256; cb += 8) {
            float qv[8]; float2 kv[8];
            #pragma unroll
            for (int m = 0; m < 8; m++) qv[m] = qw_w[(cb + m) * 256 + t];
            #pragma unroll
            for (int m = 0; m < 8; m++) kv[m] = *(const float2*)&kw_w[(cb + m) * 256 + e0];
            #pragma unroll
            for (int m = 0; m < 8; m++) { a0 += qv[m] * kv[m].x; a1 += qv[m] * kv[m].y; }
        }
        g_Aebf[(e0 + 0) * 256 + t] = __float2bfloat16(a0);
        g_Aebf[(e0 + 1) * 256 + t] = __float2bfloat16(a1);
    } else if (b == 128) {
        float acc = 0.f;
        #pragma unroll 8
        for (int d = 0; d < 256; d++)
            acc += qw_w[d * 256 + t] * __ldg(&kw_b[d]);
        g_u[t] = acc;
    } else if (b == 129) {
        float acc = 0.f;
        #pragma unroll 8
        for (int d = 0; d < 256; d++)
            acc += kw_w[d * 256 + t] * __ldg(&qw_b[d]);
        g_w[t] = acc;
    } else if (b == 130) {
        if (t < 32) {
            float cp = 0.f;
            #pragma unroll
            for (int m = 0; m < 8; m++)
                cp += qw_b[t + 32 * m] * kw_b[t + 32 * m];
            #pragma unroll
            for (int o = 16; o > 0; o >>= 1) cp += __shfl_xor_sync(0xffffffffu, cp, o);
            if (t == 0) g_c = cp;
        }
        __shared__ int nf[2];
        if (t < 2) nf[t] = 0;
        __syncthreads();
        const unsigned* mw = (const unsigned*)maskp;
        int bad0 = 0, bad1 = 0;
        for (int i = t; i < 16384; i += 256) {
            unsigned w = mw[i];
            if (w > 1u) bad0 = 1;
            if (w != 0u && w != 0x3F800000u) bad1 = 1;
        }
        if (bad0) nf[0] = 1;
        if (bad1) nf[1] = 1;
        __syncthreads();
        if (t == 0) g_mask_mode = nf[0] ? (nf[1] ? 0 : 2) : 1;
    } else {
        __shared__ float s[32][33];
        const int bb = b - 131;
        const int di = (bb >> 3) * 32, jj = (bb & 7) * 32;
        const int tx = t & 31, ty = t >> 5;
        #pragma unroll
        for (int u2 = 0; u2 < 4; u2++)
            s[ty + 8 * u2][tx] = vw_w[(di + ty + 8 * u2) * 256 + (jj + tx)];
        __syncthreads();
        #pragma unroll
        for (int u2 = 0; u2 < 4; u2++)
            g_WvT[(jj + ty + 8 * u2) * 256 + (di + tx)] = s[tx][ty + 8 * u2];
    }
}

// ---------------- qt_gemm: Q~ = q @ M via mma.sync bf16 ----------------
#define QG_B 65536
#define QG_TOT 99328

__global__ void __launch_bounds__(256, 2)
qt_gemm(const float* __restrict__ q)
{
    extern __shared__ unsigned char smem[];
    unsigned char* Ab = smem;
    unsigned* Bw = (unsigned*)(smem + QG_B);
    const int t = threadIdx.x;
    const int wid = t >> 5;
    const int lane = t & 31;
    const int lq = lane & 3, lr = lane >> 2;
    const int warpm = wid & 3, warpn = wid >> 2;
    const int tile_m = blockIdx.x >> 2;
    const int tile_n = blockIdx.x & 3;

    {
        const float4* qs = (const float4*)(q + (size_t)tile_m * 128 * 256);
        #pragma unroll 4
        for (int it = 0; it < 16; it++) {
            int idx = it * 256 + t;
            int row = idx >> 5, c = idx & 31;
            float4 fa = qs[idx * 2], fb = qs[idx * 2 + 1];
            uint4 val = make_uint4(f2bf(fa.x, fa.y), f2bf(fa.z, fa.w),
                                   f2bf(fb.x, fb.y), f2bf(fb.z, fb.w));
            *(uint4*)(Ab + row * 512 + ((c ^ (row & 7)) << 4)) = val;
        }
    }
    {
        const uint4* asrc = (const uint4*)g_Aebf;
        #pragma unroll 2
        for (int it = 0; it < 8; it++) {
            int idx = it * 256 + t;
            int er = idx >> 5, c = idx & 31;
            uint4 v = asrc[(size_t)(tile_n * 64 + er) * 32 + c];
            *(uint4*)&Bw[er * 132 + c * 4] = v;
        }
    }
    __syncthreads();

    const uint32_t Abase = smem_to_u32(Ab);
    float acc[2][4][4];
    #pragma unroll
    for (int mt = 0; mt < 2; mt++)
        #pragma unroll
        for (int nt = 0; nt < 4; nt++)
            #pragma unroll
            for (int i = 0; i < 4; i++) acc[mt][nt][i] = 0.f;

    #pragma unroll 4
    for (int ks = 0; ks < 16; ks++) {
        unsigned a0[4], a1[4];
        #pragma unroll
        for (int mt = 0; mt < 2; mt++) {
            int r = warpm * 32 + mt * 16 + (lane & 15);
            int c = ks * 2 + (lane >> 4);
            uint32_t addr = Abase + r * 512 + ((c ^ (r & 7)) << 4);
            ldsm4(mt ? a1 : a0, addr);
        }
        unsigned b0[4], b1[4];
        #pragma unroll
        for (int nt = 0; nt < 4; nt++) {
            int bi = (warpn * 32 + nt * 8 + lr) * 132 + ks * 8 + lq;
            b0[nt] = Bw[bi];
            b1[nt] = Bw[bi + 4];
        }
        #pragma unroll
        for (int nt = 0; nt < 4; nt++) {
            mma16816(acc[0][nt], a0, b0[nt], b1[nt]);
            mma16816(acc[1][nt], a1, b0[nt], b1[nt]);
        }
    }

    #pragma unroll
    for (int mt = 0; mt < 2; mt++) {
        int row = tile_m * 128 + warpm * 32 + mt * 16 + lr;
        #pragma unroll
        for (int nt = 0; nt < 4; nt++) {
            int cw = tile_n * 32 + warpn * 16 + nt * 4 + lq;
            g_Qtu[(size_t)row * 128 + cw]       = f2bf(acc[mt][nt][0], acc[mt][nt][1]);
            g_Qtu[(size_t)(row + 8) * 128 + cw] = f2bf(acc[mt][nt][2], acc[mt][nt][3]);
        }
    }
}

// ---------------- fused kernel: 2 blocks/pair, scores only ----------------
// grid = 2048: pair = b>>1, khalf = b&1 (128 k-rows each, 2 pipeline stages)
// smem (bytes):
//   [0,     32768)  kbuf0 : 64 rows x 512B bf16, chunk^(r&7)
//   [32768, 65536)  kbuf1
//   [65536, 78208)  Qtw   : 24 rows x 132 words; rows 0-15 Qt, 16 w, 17-23 zero
//   [78208, 84864)  cred  : C partials, (mt*32+lane)*13 floats
//   [84864, 84928)  a_s   : 16 floats
#define SM_QTW 65536
#define SM_CRED 78208
#define SM_A   84864
#define SM_TOT 84928

__global__ void __launch_bounds__(256, 2)
fused_kernel(const float* __restrict__ q, const float* __restrict__ k)
{
    extern __shared__ unsigned char sm[];
    unsigned char* kb0 = sm;
    unsigned* Qtw   = (unsigned*)(sm + SM_QTW);
    float*    cred  = (float*)(sm + SM_CRED);
    float*    a_s   = (float*)(sm + SM_A);

    const int pair  = blockIdx.x >> 1;
    const int khalf = blockIdx.x & 1;
    const int t = threadIdx.x;
    const int lane = t & 31;
    const int lq = lane & 3, lr = lane >> 2;
    const int w  = t >> 5;
    const int mt = w >> 1;      // m-tile 0..3
    const int kh = w & 1;       // ks-half
    const float* qb = q + (size_t)pair * QL * DD;
    const float* kb = k + ((size_t)pair * 256 + khalf * 128) * DD;

    // ---- stage Qt rows 0-15, w row 16, zero rows 17-23 ----
    {
        const uint4* qtsrc = (const uint4*)(g_Qtu + (size_t)pair * 16 * 128);
        #pragma unroll
        for (int it = 0; it < 2; it++) {
            int idx = it * 256 + t;
            int row = idx >> 5, c = idx & 31;
            *(uint4*)&Qtw[row * 132 + c * 4] = qtsrc[idx];
        }
        if (t < 128) {
            float2 wv = *(const float2*)&g_w[2 * t];
            Qtw[16 * 132 + t] = f2bf(wv.x, wv.y);
        }
        for (int i = t; i < 924; i += 256) Qtw[17 * 132 + i] = 0u;
    }

    // ---- load stage 0 into regs (all 256 threads) ----
    float4 R[16];
    {
        const float4* ks0 = (const float4*)kb;
        #pragma unroll
        for (int it = 0; it < 8; it++) {
            R[2 * it]     = ks0[(it * 256 + t) * 2];
            R[2 * it + 1] = ks0[(it * 256 + t) * 2 + 1];
        }
    }
    // a_i = q_i . u + c (warp 0)
    if (t < 32) {
        const float cc = g_c;
        for (int i = 0; i < QL; i++) {
            float p = 0.f;
            #pragma unroll
            for (int m = 0; m < 8; m++) {
                int dd = t + 32 * m;
                p += __ldg(&qb[i * 256 + dd]) * g_u[dd];
            }
            #pragma unroll
            for (int o = 16; o > 0; o >>= 1) p += __shfl_xor_sync(0xffffffffu, p, o);
            if (t == 0) a_s[i] = p + cc;
        }
    }
    // STS stage 0
    #pragma unroll
    for (int it = 0; it < 8; it++) {
        int cidx = it * 256 + t;
        int row = cidx >> 5, c = cidx & 31;
        uint4 val = make_uint4(f2bf(R[2*it].x, R[2*it].y),   f2bf(R[2*it].z, R[2*it].w),
                               f2bf(R[2*it+1].x, R[2*it+1].y), f2bf(R[2*it+1].z, R[2*it+1].w));
        *(uint4*)(kb0 + row * 512 + ((c ^ (row & 7)) << 4)) = val;
    }
    __syncthreads();

    const float a_e  = a_s[2 * lq];
    const float a_o  = a_s[2 * lq + 1];
    const float a_e8 = a_s[2 * lq + 8];
    const float a_o8 = a_s[2 * lq + 9];
    float* cr = cred + (mt * 32 + lane) * 13;
    float* taout = g_ta + (size_t)pair * 256 + khalf * 128;

    #pragma unroll
    for (int s = 0; s < 2; s++) {
        if (s < 1) {
            const float4* ksn = (const float4*)(kb + (size_t)64 * 256);
            #pragma unroll
            for (int it = 0; it < 8; it++) {
                R[2 * it]     = ksn[(it * 256 + t) * 2];
                R[2 * it + 1] = ksn[(it * 256 + t) * 2 + 1];
            }
        }
        const uint32_t kbase = smem_to_u32(kb0 + (s & 1) * 32768);
        float c0[4], c1[4], cw[4];
        #pragma unroll
        for (int i = 0; i < 4; i++) { c0[i] = 0.f; c1[i] = 0.f; cw[i] = 0.f; }
        const int krow = mt * 16 + (lane & 15);
        #pragma unroll
        for (int ki = 0; ki < 8; ki++) {
            const int ksx = kh * 8 + ki;
            unsigned a[4];
            int c = ksx * 2 + (lane >> 4);
            ldsm4(a, kbase + krow * 512 + ((c ^ (krow & 7)) << 4));
            int w0 = lr * 132 + ksx * 8 + lq;
            unsigned b00 = Qtw[w0],             b01 = Qtw[w0 + 4];
            unsigned b10 = Qtw[w0 + 8 * 132],   b11 = Qtw[w0 + 8 * 132 + 4];
            unsigned b20 = Qtw[w0 + 16 * 132],  b21 = Qtw[w0 + 16 * 132 + 4];
            mma16816(c0, a, b00, b01);
            mma16816(c1, a, b10, b11);
            mma16816(cw, a, b20, b21);
        }
        if (kh == 1) {
            #pragma unroll
            for (int j = 0; j < 4; j++) { cr[j] = c0[j]; cr[4 + j] = c1[j]; cr[8 + j] = cw[j]; }
        }
        __syncthreads();
        if (kh == 0) {
            #pragma unroll
            for (int j = 0; j < 4; j++) { c0[j] += cr[j]; c1[j] += cr[4 + j]; cw[j] += cr[8 + j]; }
            float mr  = fmaxf(fmaxf(c0[0] + a_e, c0[1] + a_o), fmaxf(c1[0] + a_e8, c1[1] + a_o8));
            float mr8 = fmaxf(fmaxf(c0[2] + a_e, c0[3] + a_o), fmaxf(c1[2] + a_e8, c1[3] + a_o8));
            mr  = fmaxf(mr,  __shfl_xor_sync(0xffffffffu, mr, 1));
            mr  = fmaxf(mr,  __shfl_xor_sync(0xffffffffu, mr, 2));
            mr8 = fmaxf(mr8, __shfl_xor_sync(0xffffffffu, mr8, 1));
            mr8 = fmaxf(mr8, __shfl_xor_sync(0xffffffffu, mr8, 2));
            float wkr  = __shfl_sync(0xffffffffu, cw[0], lane & ~3);
            float wkr8 = __shfl_sync(0xffffffffu, cw[2], lane & ~3);
            if (lq == 0) {
                taout[s * 64 + mt * 16 + lr]     = wkr + mr;
                taout[s * 64 + mt * 16 + lr + 8] = wkr8 + mr8;
            }
        }
        if (s < 1) {
            unsigned char* nbuf = kb0 + 32768;
            #pragma unroll
            for (int it = 0; it < 8; it++) {
                int cidx = it * 256 + t;
                int row = cidx >> 5, c = cidx & 31;
                uint4 val = make_uint4(f2bf(R[2*it].x, R[2*it].y),   f2bf(R[2*it].z, R[2*it].w),
                                       f2bf(R[2*it+1].x, R[2*it+1].y), f2bf(R[2*it+1].z, R[2*it+1].w));
                *(uint4*)(nbuf + row * 512 + ((c ^ (row & 7)) << 4)) = val;
            }
        }
        __syncthreads();
    }
}

// ---------------- softmax kernel: normalize, mask, softmax ----------------
__device__ __forceinline__ float bsum(float v, float* red, int t) {
    __syncthreads();
    #pragma unroll
    for (int o = 16; o > 0; o >>= 1) v += __shfl_xor_sync(0xffffffffu, v, o);
    if ((t & 31) == 0) red[t >> 5] = v;
    __syncthreads();
    float r = red[0];
    #pragma unroll
    for (int i = 1; i < 8; i++) r += red[i];
    return r;
}
__device__ __forceinline__ float bmax(float v, float* red, int t) {
    __syncthreads();
    #pragma unroll
    for (int o = 16; o > 0; o >>= 1) v = fmaxf(v, __shfl_xor_sync(0xffffffffu, v, o));
    if ((t & 31) == 0) red[t >> 5] = v;
    __syncthreads();
    float r = red[0];
    #pragma unroll
    for (int i = 1; i < 8; i++) r = fmaxf(r, red[i]);
    return r;
}

__global__ void __launch_bounds__(256)
softmax_kernel(const void* __restrict__ maskp)
{
    __shared__ float red_s[8];
    const int pair = blockIdx.x;
    const int t = threadIdx.x;
    float tv = g_ta[(size_t)pair * 256 + t];
    float ss = bsum(tv * tv, red_s, t);
    float inv = rsqrtf(ss);
    const int mm = g_mask_mode;
    bool masked;
    size_t mi = (size_t)pair * 256 + t;
    if (mm == 0)      masked = ((const unsigned char*)maskp)[mi] != 0;
    else if (mm == 1) masked = ((const int*)maskp)[mi] != 0;
    else              masked = ((const float*)maskp)[mi] != 0.f;
    float x = masked ? -10.f : tv * inv;
    float cnt = bsum(masked ? 0.f : 1.f, red_s, t);
    float mx = bmax(x, red_s, t);
    float ex = __expf(x - mx);
    float se = bsum(ex, red_s, t);
    float attn = (cnt == 0.f) ? 0.f : ex / se;
    g_attn[(size_t)pair * 256 + t] = attn;
    if (t == 0) g_sA[pair] = (cnt > 0.f) ? 1.f : 0.f;
}

// ---------------- av_kernel: tvec partials, pure v stream (R13) ----------------
__global__ void __launch_bounds__(256)
av_kernel(const float* __restrict__ v)
{
    __shared__ float at[128];
    const int t = threadIdx.x;
    const int pair = blockIdx.x >> 1;
    const int half = blockIdx.x & 1;
    if (t < 128) at[t] = g_attn[(size_t)pair * 256 + half * 128 + t];
    __syncthreads();
    const float* vb = v + ((size_t)pair * 256 + half * 128) * 256;
    float acc = 0.f;
    #pragma unroll 16
    for (int r = 0; r < 128; r++)
        acc += at[r] * vb[r * 256 + t];
    g_tvh[(size_t)half * PAIRS * 256 + (size_t)pair * 256 + t] = acc;
}

// ---------------- out stage 1: partials over 128-j chunks (split-K=2) ----------------
__global__ void __launch_bounds__(256)
out_part_kernel()
{
    __shared__ float tv[128 * 17];
    const int t = threadIdx.x;
    const int kc = blockIdx.x & 1;
    const int cg = (blockIdx.x >> 1) & 3;
    const int pg = blockIdx.x >> 3;
    const int p0 = pg * 16;
    const int c0 = cg * 64;
    const int j0 = kc * 128;
    const int c  = c0 + (t & 63);
    const int rg = t >> 6;

    #pragma unroll
    for (int it = 0; it < 8; it++) {
        int idx = it * 256 + t;
        int r = idx >> 7, j = idx & 127;
        size_t e = (size_t)(p0 + r) * 256 + j0 + j;
        tv[j * 17 + r] = g_tvh[e] + g_tvh[(size_t)PAIRS * 256 + e];
    }
    __syncthreads();
    float acc0 = 0.f, acc1 = 0.f, acc2 = 0.f, acc3 = 0.f;
    const float* Wcol = g_WvT + (size_t)j0 * 256 + c;
    #pragma unroll 8
    for (int j = 0; j < 128; j++) {
        float wv = __ldg(&Wcol[j * 256]);
        const float* T = &tv[j * 17];
        acc0 += T[rg]      * wv;
        acc1 += T[rg + 4]  * wv;
        acc2 += T[rg + 8]  * wv;
        acc3 += T[rg + 12] * wv;
    }
    float* op = g_opart + (size_t)kc * PAIRS * 256;
    op[(size_t)(p0 + rg)      * 256 + c] = acc0;
    op[(size_t)(p0 + rg + 4)  * 256 + c] = acc1;
    op[(size_t)(p0 + rg + 8)  * 256 + c] = acc2;
    op[(size_t)(p0 + rg + 12) * 256 + c] = acc3;
}

// ---------------- out stage 2: sum partials + bias ----------------
__global__ void __launch_bounds__(256)
out_sum_kernel(const float* __restrict__ vw_b, float* __restrict__ out)
{
    const int t = threadIdx.x;
    const int o0 = blockIdx.x * 1024 + t;
    #pragma unroll
    for (int it = 0; it < 4; it++) {
        int o = o0 + it * 256;
        int row = o >> 8, c = o & 255;
        float s = g_opart[o] + g_opart[o + PAIRS * 256];
        out[o] = s + g_sA[row] * __ldg(&vw_b[c]);
    }
}

extern "C" void kernel_launch(void* const* d_in, const int* in_sizes, int n_in,
                              void* d_out, int out_size)
{
    const float* q    = (const float*)d_in[0];
    const float* k    = (const float*)d_in[1];
    const float* v    = (const float*)d_in[2];
    const void*  m    = d_in[3];
    const float* qw_w = (const float*)d_in[4];
    const float* qw_b = (const float*)d_in[5];
    const float* kw_w = (const float*)d_in[6];
    const float* kw_b = (const float*)d_in[7];
    const float* vw_w = (const float*)d_in[8];
    const float* vw_b = (const float*)d_in[9];
    float* out = (float*)d_out;
    (void)in_sizes; (void)n_in; (void)out_size;

    cudaFuncSetAttribute(qt_gemm, cudaFuncAttributeMaxDynamicSharedMemorySize, QG_TOT);
    cudaFuncSetAttribute(fused_kernel, cudaFuncAttributeMaxDynamicSharedMemorySize, SM_TOT);

    setup_kernel<<<195, 256>>>(qw_w, qw_b, kw_w, kw_b, vw_w, m);
    qt_gemm<<<512, 256, QG_TOT>>>(q);
    fused_kernel<<<2048, 256, SM_TOT>>>(q, k);
    softmax_kernel<<<PAIRS, 256>>>(m);
    av_kernel<<<2048, 256>>>(v);
    out_part_kernel<<<512, 256>>>();
    out_sum_kernel<<<256, 256>>>(vw_b, out);
}

// round 17
// speedup vs baseline: 1.2539x; 1.2539x over previous
#include <cuda_runtime.h>
#include <cuda_bf16.h>
#include <cstdint>

typedef unsigned long long ull;

#define PAIRS 1024
#define DD 256
#define QL 16

// ---------------- persistent scratch / precomputed ----------------
__device__ __nv_bfloat16 g_Aebf[256 * 256];  // M^T: [e][d] = M[d][e], bf16 (MMA B operand)
__device__ float    g_WvT[256 * 256];        // WvT[j][d] = vw_w[d][j]
__device__ float    g_u[256];
__device__ float    g_w[256];
__device__ float    g_c;
__device__ int      g_mask_mode;             // 0=u8 bool, 1=int32, 2=float32
__device__ unsigned g_Qtu[16384 * 128];      // Q-tilde bf16x2 words
__device__ float    g_ai[16384];             // a_i = q_i.u + c per global q-row
__device__ float    g_attn[PAIRS * 256];     // softmax weights per pair
__device__ float    g_tvh[2 * PAIRS * 256];  // attn.v partials per v-half
__device__ float    g_sA[PAIRS];             // 1 if any unmasked else 0
__device__ float    g_opart[4 * PAIRS * 256];// split-K partials [kc][row][c]

__device__ __forceinline__ unsigned f2bf(float a, float b) {
    __nv_bfloat162 h = __floats2bfloat162_rn(a, b);
    return *reinterpret_cast<unsigned*>(&h);
}
__device__ __forceinline__ float2 bf2f2(unsigned u) {
    float2 r;
    r.x = __uint_as_float(u << 16);
    r.y = __uint_as_float(u & 0xFFFF0000u);
    return r;
}
__device__ __forceinline__ uint32_t smem_to_u32(const void* p) {
    uint32_t a;
    asm("{ .reg .u64 tmp; cvta.to.shared.u64 tmp, %1; cvt.u32.u64 %0, tmp; }" : "=r"(a) : "l"(p));
    return a;
}
__device__ __forceinline__ void ldsm4(unsigned* r, uint32_t addr) {
    asm volatile("ldmatrix.sync.aligned.m8n8.x4.shared.b16 {%0,%1,%2,%3}, [%4];"
        : "=r"(r[0]), "=r"(r[1]), "=r"(r[2]), "=r"(r[3]) : "r"(addr));
}
__device__ __forceinline__ void mma16816(float* c, const unsigned* a, unsigned b0, unsigned b1) {
    asm volatile(
        "mma.sync.aligned.m16n8k16.row.col.f32.bf16.bf16.f32 "
        "{%0,%1,%2,%3}, {%4,%5,%6,%7}, {%8,%9}, {%0,%1,%2,%3};"
        : "+f"(c[0]), "+f"(c[1]), "+f"(c[2]), "+f"(c[3])
        : "r"(a[0]), "r"(a[1]), "r"(a[2]), "r"(a[3]), "r"(b0), "r"(b1));
}

// ---------------- setup kernel ----------------
__global__ void setup_kernel(const float* __restrict__ qw_w, const float* __restrict__ qw_b,
                             const float* __restrict__ kw_w, const float* __restrict__ kw_b,
                             const float* __restrict__ vw_w, const void* __restrict__ maskp)
{
    const int b = blockIdx.x;
    const int t = threadIdx.x;
    if (b < 128) {
        const int e0 = b * 2;
        float a0 = 0.f, a1 = 0.f;
        for (int cb = 0; cb < 256; cb += 8) {
            float qv[8]; float2 kv[8];
            #pragma unroll
            for (int m = 0; m < 8; m++) qv[m] = qw_w[(cb + m) * 256 + t];
            #pragma unroll
            for (int m = 0; m < 8; m++) kv[m] = *(const float2*)&kw_w[(cb + m) * 256 + e0];
            #pragma unroll
            for (int m = 0; m < 8; m++) { a0 += qv[m] * kv[m].x; a1 += qv[m] * kv[m].y; }
        }
        g_Aebf[(e0 + 0) * 256 + t] = __float2bfloat16(a0);
        g_Aebf[(e0 + 1) * 256 + t] = __float2bfloat16(a1);
    } else if (b == 128) {
        float acc = 0.f;
        #pragma unroll 8
        for (int d = 0; d < 256; d++)
            acc += qw_w[d * 256 + t] * __ldg(&kw_b[d]);
        g_u[t] = acc;
    } else if (b == 129) {
        float acc = 0.f;
        #pragma unroll 8
        for (int d = 0; d < 256; d++)
            acc += kw_w[d * 256 + t] * __ldg(&qw_b[d]);
        g_w[t] = acc;
    } else if (b == 130) {
        if (t < 32) {
            float cp = 0.f;
            #pragma unroll
            for (int m = 0; m < 8; m++)
                cp += qw_b[t + 32 * m] * kw_b[t + 32 * m];
            #pragma unroll
            for (int o = 16; o > 0; o >>= 1) cp += __shfl_xor_sync(0xffffffffu, cp, o);
            if (t == 0) g_c = cp;
        }
        __shared__ int nf[2];
        if (t < 2) nf[t] = 0;
        __syncthreads();
        const unsigned* mw = (const unsigned*)maskp;
        int bad0 = 0, bad1 = 0;
        for (int i = t; i < 16384; i += 256) {
            unsigned w = mw[i];
            if (w > 1u) bad0 = 1;
            if (w != 0u && w != 0x3F800000u) bad1 = 1;
        }
        if (bad0) nf[0] = 1;
        if (bad1) nf[1] = 1;
        __syncthreads();
        if (t == 0) g_mask_mode = nf[0] ? (nf[1] ? 0 : 2) : 1;
    } else {
        __shared__ float s[32][33];
        const int bb = b - 131;
        const int di = (bb >> 3) * 32, jj = (bb & 7) * 32;
        const int tx = t & 31, ty = t >> 5;
        #pragma unroll
        for (int u2 = 0; u2 < 4; u2++)
            s[ty + 8 * u2][tx] = vw_w[(di + ty + 8 * u2) * 256 + (jj + tx)];
        __syncthreads();
        #pragma unroll
        for (int u2 = 0; u2 < 4; u2++)
            g_WvT[(jj + ty + 8 * u2) * 256 + (di + tx)] = s[tx][ty + 8 * u2];
    }
}

// ---------------- qt_gemm: Q~ = q @ M via mma.sync bf16 (+ a_i epilogue) ----------------
#define QG_B 65536
#define QG_TOT 99328

__global__ void __launch_bounds__(256, 2)
qt_gemm(const float* __restrict__ q)
{
    extern __shared__ unsigned char smem[];
    unsigned char* Ab = smem;
    unsigned* Bw = (unsigned*)(smem + QG_B);
    const int t = threadIdx.x;
    const int wid = t >> 5;
    const int lane = t & 31;
    const int lq = lane & 3, lr = lane >> 2;
    const int warpm = wid & 3, warpn = wid >> 2;
    const int tile_m = blockIdx.x >> 2;
    const int tile_n = blockIdx.x & 3;

    {
        const float4* qs = (const float4*)(q + (size_t)tile_m * 128 * 256);
        #pragma unroll 4
        for (int it = 0; it < 16; it++) {
            int idx = it * 256 + t;
            int row = idx >> 5, c = idx & 31;
            float4 fa = qs[idx * 2], fb = qs[idx * 2 + 1];
            uint4 val = make_uint4(f2bf(fa.x, fa.y), f2bf(fa.z, fa.w),
                                   f2bf(fb.x, fb.y), f2bf(fb.z, fb.w));
            *(uint4*)(Ab + row * 512 + ((c ^ (row & 7)) << 4)) = val;
        }
    }
    {
        const uint4* asrc = (const uint4*)g_Aebf;
        #pragma unroll 2
        for (int it = 0; it < 8; it++) {
            int idx = it * 256 + t;
            int er = idx >> 5, c = idx & 31;
            uint4 v = asrc[(size_t)(tile_n * 64 + er) * 32 + c];
            *(uint4*)&Bw[er * 132 + c * 4] = v;
        }
    }
    __syncthreads();

    const uint32_t Abase = smem_to_u32(Ab);
    float acc[2][4][4];
    #pragma unroll
    for (int mt = 0; mt < 2; mt++)
        #pragma unroll
        for (int nt = 0; nt < 4; nt++)
            #pragma unroll
            for (int i = 0; i < 4; i++) acc[mt][nt][i] = 0.f;

    #pragma unroll 4
    for (int ks = 0; ks < 16; ks++) {
        unsigned a0[4], a1[4];
        #pragma unroll
        for (int mt = 0; mt < 2; mt++) {
            int r = warpm * 32 + mt * 16 + (lane & 15);
            int c = ks * 2 + (lane >> 4);
            uint32_t addr = Abase + r * 512 + ((c ^ (r & 7)) << 4);
            ldsm4(mt ? a1 : a0, addr);
        }
        unsigned b0[4], b1[4];
        #pragma unroll
        for (int nt = 0; nt < 4; nt++) {
            int bi = (warpn * 32 + nt * 8 + lr) * 132 + ks * 8 + lq;
            b0[nt] = Bw[bi];
            b1[nt] = Bw[bi + 4];
        }
        #pragma unroll
        for (int nt = 0; nt < 4; nt++) {
            mma16816(acc[0][nt], a0, b0[nt], b1[nt]);
            mma16816(acc[1][nt], a1, b0[nt], b1[nt]);
        }
    }

    #pragma unroll
    for (int mt = 0; mt < 2; mt++) {
        int row = tile_m * 128 + warpm * 32 + mt * 16 + lr;
        #pragma unroll
        for (int nt = 0; nt < 4; nt++) {
            int cw = tile_n * 32 + warpn * 16 + nt * 4 + lq;
            g_Qtu[(size_t)row * 128 + cw]       = f2bf(acc[mt][nt][0], acc[mt][nt][1]);
            g_Qtu[(size_t)(row + 8) * 128 + cw] = f2bf(acc[mt][nt][2], acc[mt][nt][3]);
        }
    }

    // ---- a_i epilogue (tile_n==0 blocks): a_row = q_row . u + c, from staged Ab ----
    if (tile_n == 0) {
        const float cc = g_c;
        const float* up = &g_u[lane * 8];
        #pragma unroll 4
        for (int rr = 0; rr < 16; rr++) {
            int row = wid * 16 + rr;
            uint4 hv = *(const uint4*)(Ab + row * 512 + ((lane ^ (row & 7)) << 4));
            float2 f;
            float s = 0.f;
            f = bf2f2(hv.x); s += f.x * up[0] + f.y * up[1];
            f = bf2f2(hv.y); s += f.x * up[2] + f.y * up[3];
            f = bf2f2(hv.z); s += f.x * up[4] + f.y * up[5];
            f = bf2f2(hv.w); s += f.x * up[6] + f.y * up[7];
            #pragma unroll
            for (int o = 16; o > 0; o >>= 1) s += __shfl_xor_sync(0xffffffffu, s, o);
            if (lane == 0) g_ai[tile_m * 128 + row] = s + cc;
        }
    }
}

// ---------------- fused kernel: all-warp pipelined scores + softmax (R13) ----------------
// smem (bytes):
//   [0,     32768)  kbuf0 : 64 rows x 512B bf16, chunk^(r&7)
//   [32768, 65536)  kbuf1
//   [65536, 78208)  Qtw   : 24 rows x 132 words; rows 0-15 Qt, 16 w, 17-23 zero
//   [78208, 84864)  cred  : C partials, (mt*32+lane)*13 floats
//   [84864, 84928)  a_s   : 16 floats
//   [84928, 85952)  ta_s  : 256 floats
//   [85952, 85984)  red   : 8 floats
#define SM_QTW 65536
#define SM_CRED 78208
#define SM_A   84864
#define SM_TA  84928
#define SM_RED 85952
#define SM_TOT 85984

__device__ __forceinline__ float bsum(float v, float* red, int t) {
    __syncthreads();
    #pragma unroll
    for (int o = 16; o > 0; o >>= 1) v += __shfl_xor_sync(0xffffffffu, v, o);
    if ((t & 31) == 0) red[t >> 5] = v;
    __syncthreads();
    float r = red[0];
    #pragma unroll
    for (int i = 1; i < 8; i++) r += red[i];
    return r;
}
__device__ __forceinline__ float bmax(float v, float* red, int t) {
    __syncthreads();
    #pragma unroll
    for (int o = 16; o > 0; o >>= 1) v = fmaxf(v, __shfl_xor_sync(0xffffffffu, v, o));
    if ((t & 31) == 0) red[t >> 5] = v;
    __syncthreads();
    float r = red[0];
    #pragma unroll
    for (int i = 1; i < 8; i++) r = fmaxf(r, red[i]);
    return r;
}

__global__ void __launch_bounds__(256, 2)
fused_kernel(const float* __restrict__ k, const void* __restrict__ maskp)
{
    extern __shared__ unsigned char sm[];
    unsigned char* kb0 = sm;
    unsigned* Qtw   = (unsigned*)(sm + SM_QTW);
    float*    cred  = (float*)(sm + SM_CRED);
    float*    a_s   = (float*)(sm + SM_A);
    float*    ta_s  = (float*)(sm + SM_TA);
    float*    red_s = (float*)(sm + SM_RED);

    const int pair = blockIdx.x;
    const int t = threadIdx.x;
    const int lane = t & 31;
    const int lq = lane & 3, lr = lane >> 2;
    const int w  = t >> 5;
    const int mt = w >> 1;      // m-tile 0..3
    const int kh = w & 1;       // ks-half
    const float* kb = k + (size_t)pair * 256 * DD;

    // ---- stage Qt rows 0-15, w row 16, zero rows 17-23; a_s from g_ai ----
    {
        const uint4* qtsrc = (const uint4*)(g_Qtu + (size_t)pair * 16 * 128);
        #pragma unroll
        for (int it = 0; it < 2; it++) {
            int idx = it * 256 + t;
            int row = idx >> 5, c = idx & 31;
            *(uint4*)&Qtw[row * 132 + c * 4] = qtsrc[idx];
        }
        if (t < 128) {
            float2 wv = *(const float2*)&g_w[2 * t];
            Qtw[16 * 132 + t] = f2bf(wv.x, wv.y);
        }
        for (int i = t; i < 924; i += 256) Qtw[17 * 132 + i] = 0u;
        if (t < 16) a_s[t] = g_ai[pair * 16 + t];
    }

    // ---- load stage 0 into regs (all 256 threads) ----
    float4 R[16];
    {
        const float4* ks0 = (const float4*)kb;
        #pragma unroll
        for (int it = 0; it < 8; it++) {
            R[2 * it]     = ks0[(it * 256 + t) * 2];
            R[2 * it + 1] = ks0[(it * 256 + t) * 2 + 1];
        }
    }
    // STS stage 0
    #pragma unroll
    for (int it = 0; it < 8; it++) {
        int cidx = it * 256 + t;
        int row = cidx >> 5, c = cidx & 31;
        uint4 val = make_uint4(f2bf(R[2*it].x, R[2*it].y),   f2bf(R[2*it].z, R[2*it].w),
                               f2bf(R[2*it+1].x, R[2*it+1].y), f2bf(R[2*it+1].z, R[2*it+1].w));
        *(uint4*)(kb0 + row * 512 + ((c ^ (row & 7)) << 4)) = val;
    }
    __syncthreads();

    const float a_e  = a_s[2 * lq];
    const float a_o  = a_s[2 * lq + 1];
    const float a_e8 = a_s[2 * lq + 8];
    const float a_o8 = a_s[2 * lq + 9];
    float* cr = cred + (mt * 32 + lane) * 13;

    #pragma unroll
    for (int s = 0; s < 4; s++) {
        if (s < 3) {
            const float4* ksn = (const float4*)(kb + (size_t)(64 * (s + 1)) * 256);
            #pragma unroll
            for (int it = 0; it < 8; it++) {
                R[2 * it]     = ksn[(it * 256 + t) * 2];
                R[2 * it + 1] = ksn[(it * 256 + t) * 2 + 1];
            }
        }
        const uint32_t kbase = smem_to_u32(kb0 + (s & 1) * 32768);
        float c0[4], c1[4], cw[4];
        #pragma unroll
        for (int i = 0; i < 4; i++) { c0[i] = 0.f; c1[i] = 0.f; cw[i] = 0.f; }
        const int krow = mt * 16 + (lane & 15);
        #pragma unroll
        for (int ki = 0; ki < 8; ki++) {
            const int ksx = kh * 8 + ki;
            unsigned a[4];
            int c = ksx * 2 + (lane >> 4);
            ldsm4(a, kbase + krow * 512 + ((c ^ (krow & 7)) << 4));
            int w0 = lr * 132 + ksx * 8 + lq;
            unsigned b00 = Qtw[w0],             b01 = Qtw[w0 + 4];
            unsigned b10 = Qtw[w0 + 8 * 132],   b11 = Qtw[w0 + 8 * 132 + 4];
            unsigned b20 = Qtw[w0 + 16 * 132],  b21 = Qtw[w0 + 16 * 132 + 4];
            mma16816(c0, a, b00, b01);
            mma16816(c1, a, b10, b11);
            mma16816(cw, a, b20, b21);
        }
        if (kh == 1) {
            #pragma unroll
            for (int j = 0; j < 4; j++) { cr[j] = c0[j]; cr[4 + j] = c1[j]; cr[8 + j] = cw[j]; }
        }
        __syncthreads();
        if (kh == 0) {
            #pragma unroll
            for (int j = 0; j < 4; j++) { c0[j] += cr[j]; c1[j] += cr[4 + j]; cw[j] += cr[8 + j]; }
            float mr  = fmaxf(fmaxf(c0[0] + a_e, c0[1] + a_o), fmaxf(c1[0] + a_e8, c1[1] + a_o8));
            float mr8 = fmaxf(fmaxf(c0[2] + a_e, c0[3] + a_o), fmaxf(c1[2] + a_e8, c1[3] + a_o8));
            mr  = fmaxf(mr,  __shfl_xor_sync(0xffffffffu, mr, 1));
            mr  = fmaxf(mr,  __shfl_xor_sync(0xffffffffu, mr, 2));
            mr8 = fmaxf(mr8, __shfl_xor_sync(0xffffffffu, mr8, 1));
            mr8 = fmaxf(mr8, __shfl_xor_sync(0xffffffffu, mr8, 2));
            float wkr  = __shfl_sync(0xffffffffu, cw[0], lane & ~3);
            float wkr8 = __shfl_sync(0xffffffffu, cw[2], lane & ~3);
            if (lq == 0) {
                ta_s[s * 64 + mt * 16 + lr]     = wkr + mr;
                ta_s[s * 64 + mt * 16 + lr + 8] = wkr8 + mr8;
            }
        }
        if (s < 3) {
            unsigned char* nbuf = kb0 + ((s + 1) & 1) * 32768;
            #pragma unroll
            for (int it = 0; it < 8; it++) {
                int cidx = it * 256 + t;
                int row = cidx >> 5, c = cidx & 31;
                uint4 val = make_uint4(f2bf(R[2*it].x, R[2*it].y),   f2bf(R[2*it].z, R[2*it].w),
                                       f2bf(R[2*it+1].x, R[2*it+1].y), f2bf(R[2*it+1].z, R[2*it+1].w));
                *(uint4*)(nbuf + row * 512 + ((c ^ (row & 7)) << 4)) = val;
            }
        }
        __syncthreads();
    }

    // ---- normalize, mask, softmax (all 256); write attn + sA ----
    {
        float tv = ta_s[t];
        float ss = bsum(tv * tv, red_s, t);
        float inv = rsqrtf(ss);
        const int mm = g_mask_mode;
        bool masked;
        size_t mi = (size_t)pair * 256 + t;
        if (mm == 0)      masked = ((const unsigned char*)maskp)[mi] != 0;
        else if (mm == 1) masked = ((const int*)maskp)[mi] != 0;
        else              masked = ((const float*)maskp)[mi] != 0.f;
        float x = masked ? -10.f : tv * inv;
        float cnt = bsum(masked ? 0.f : 1.f, red_s, t);
        float mx = bmax(x, red_s, t);
        float ex = __expf(x - mx);
        float se = bsum(ex, red_s, t);
        float attn = (cnt == 0.f) ? 0.f : ex / se;
        g_attn[(size_t)pair * 256 + t] = attn;
        if (t == 0) g_sA[pair] = (cnt > 0.f) ? 1.f : 0.f;
    }
}

// ---------------- av_kernel: tvec partials, pure v stream (R13) ----------------
__global__ void __launch_bounds__(256)
av_kernel(const float* __restrict__ v)
{
    __shared__ float at[128];
    const int t = threadIdx.x;
    const int pair = blockIdx.x >> 1;
    const int half = blockIdx.x & 1;
    if (t < 128) at[t] = g_attn[(size_t)pair * 256 + half * 128 + t];
    __syncthreads();
    const float* vb = v + ((size_t)pair * 256 + half * 128) * 256;
    float acc = 0.f;
    #pragma unroll 16
    for (int r = 0; r < 128; r++)
        acc += at[r] * vb[r * 256 + t];
    g_tvh[(size_t)half * PAIRS * 256 + (size_t)pair * 256 + t] = acc;
}

// ---------------- out stage 1: partials over 64-j chunks (split-K=4, R13) ----------------
__global__ void __launch_bounds__(256)
out_part_kernel()
{
    __shared__ float tv[64 * 17];
    const int t = threadIdx.x;
    const int kc = blockIdx.x & 3;
    const int cg = (blockIdx.x >> 2) & 3;
    const int pg = blockIdx.x >> 4;
    const int p0 = pg * 16;
    const int c0 = cg * 64;
    const int j0 = kc * 64;
    const int c  = c0 + (t & 63);
    const int rg = t >> 6;

    #pragma unroll
    for (int it = 0; it < 4; it++) {
        int idx = it * 256 + t;
        int r = idx >> 6, j = idx & 63;
        size_t e = (size_t)(p0 + r) * 256 + j0 + j;
        tv[j * 17 + r] = g_tvh[e] + g_tvh[(size_t)PAIRS * 256 + e];
    }
    __syncthreads();
    float acc0 = 0.f, acc1 = 0.f, acc2 = 0.f, acc3 = 0.f;
    const float* Wcol = g_WvT + (size_t)j0 * 256 + c;
    #pragma unroll 8
    for (int j = 0; j < 64; j++) {
        float wv = __ldg(&Wcol[j * 256]);
        const float* T = &tv[j * 17];
        acc0 += T[rg]      * wv;
        acc1 += T[rg + 4]  * wv;
        acc2 += T[rg + 8]  * wv;
        acc3 += T[rg + 12] * wv;
    }
    float* op = g_opart + (size_t)kc * PAIRS * 256;
    op[(size_t)(p0 + rg)      * 256 + c] = acc0;
    op[(size_t)(p0 + rg + 4)  * 256 + c] = acc1;
    op[(size_t)(p0 + rg + 8)  * 256 + c] = acc2;
    op[(size_t)(p0 + rg + 12) * 256 + c] = acc3;
}

// ---------------- out stage 2: sum partials + bias ----------------
__global__ void __launch_bounds__(256)
out_sum_kernel(const float* __restrict__ vw_b, float* __restrict__ out)
{
    const int t = threadIdx.x;
    const int o0 = blockIdx.x * 1024 + t;
    #pragma unroll
    for (int it = 0; it < 4; it++) {
        int o = o0 + it * 256;
        int row = o >> 8, c = o & 255;
        float s = g_opart[o] + g_opart[o + PAIRS * 256]
                + g_opart[o + 2 * PAIRS * 256] + g_opart[o + 3 * PAIRS * 256];
        out[o] = s + g_sA[row] * __ldg(&vw_b[c]);
    }
}

extern "C" void kernel_launch(void* const* d_in, const int* in_sizes, int n_in,
                              void* d_out, int out_size)
{
    const float* q    = (const float*)d_in[0];
    const float* k    = (const float*)d_in[1];
    const float* v    = (const float*)d_in[2];
    const void*  m    = d_in[3];
    const float* qw_w = (const float*)d_in[4];
    const float* qw_b = (const float*)d_in[5];
    const float* kw_w = (const float*)d_in[6];
    const float* kw_b = (const float*)d_in[7];
    const float* vw_w = (const float*)d_in[8];
    const float* vw_b = (const float*)d_in[9];
    float* out = (float*)d_out;
    (void)in_sizes; (void)n_in; (void)out_size;

    cudaFuncSetAttribute(qt_gemm, cudaFuncAttributeMaxDynamicSharedMemorySize, QG_TOT);
    cudaFuncSetAttribute(fused_kernel, cudaFuncAttributeMaxDynamicSharedMemorySize, SM_TOT);

    setup_kernel<<<195, 256>>>(qw_w, qw_b, kw_w, kw_b, vw_w, m);
    qt_gemm<<<512, 256, QG_TOT>>>(q);
    fused_kernel<<<PAIRS, 256, SM_TOT>>>(k, m);
    av_kernel<<<2048, 256>>>(v);
    out_part_kernel<<<1024, 256>>>();
    out_sum_kernel<<<256, 256>>>(vw_b, out);
}